// round 1
// baseline (speedup 1.0000x reference)
#include <cuda_runtime.h>
#include <math_constants.h>

// Global accumulator (no cudaMalloc allowed).
__device__ double g_eme_sum;

__global__ void eme_zero_kernel() {
    g_eme_sum = 0.0;
}

// One thread per 8x8 window. Input logical shape (32,3,1024,1024) fp32,
// treated as 96 images of 1024x1024. Windows per image: 128x128.
__global__ __launch_bounds__(256) void eme_main_kernel(
    const float* __restrict__ y, int n_windows)
{
    const int w = blockIdx.x * 256 + threadIdx.x;

    float val = 0.0f;
    if (w < n_windows) {
        const int img = w >> 14;          // / 16384 windows per image
        const int rem = w & 16383;
        const int wy  = rem >> 7;         // window row 0..127
        const int wx  = rem & 127;        // window col 0..127

        const float4* __restrict__ p = reinterpret_cast<const float4*>(
            y + (size_t)img * 1048576u + (size_t)wy * 8192u + (size_t)wx * 8u);
        // row stride = 1024 floats = 256 float4

        float mx = -CUDART_INF_F;
        float mn =  CUDART_INF_F;
        #pragma unroll
        for (int r = 0; r < 8; r++) {
            float4 a = p[r * 256];
            float4 b = p[r * 256 + 1];
            mx = fmaxf(mx, fmaxf(fmaxf(a.x, a.y), fmaxf(a.z, a.w)));
            mn = fminf(mn, fminf(fminf(a.x, a.y), fminf(a.z, a.w)));
            mx = fmaxf(mx, fmaxf(fmaxf(b.x, b.y), fmaxf(b.z, b.w)));
            mn = fminf(mn, fminf(fminf(b.x, b.y), fminf(b.z, b.w)));
        }

        if (mx != mn) {
            val = 20.0f * logf(mx / (mn + 1e-4f));
        }
    }

    // Intra-warp reduction (fp32: 256 values of O(100) -> fine).
    #pragma unroll
    for (int o = 16; o > 0; o >>= 1)
        val += __shfl_xor_sync(0xffffffffu, val, o);

    __shared__ float warp_sums[8];
    const int lane = threadIdx.x & 31;
    const int wid  = threadIdx.x >> 5;
    if (lane == 0) warp_sums[wid] = val;
    __syncthreads();

    if (wid == 0) {
        float v = (lane < 8) ? warp_sums[lane] : 0.0f;
        #pragma unroll
        for (int o = 4; o > 0; o >>= 1)
            v += __shfl_xor_sync(0xffffffffu, v, o);
        if (lane == 0)
            atomicAdd(&g_eme_sum, (double)v);
    }
}

__global__ void eme_finish_kernel(float* __restrict__ out) {
    // result = sum / (B * row * col / (w*w)) = sum / (32 * 1048576 / 64)
    out[0] = (float)(g_eme_sum * (1.0 / 524288.0));
}

extern "C" void kernel_launch(void* const* d_in, const int* in_sizes, int n_in,
                              void* d_out, int out_size)
{
    const float* y = (const float*)d_in[0];
    float* out = (float*)d_out;

    const int n_windows = 32 * 3 * 128 * 128;  // 1,572,864
    const int threads = 256;
    const int blocks = (n_windows + threads - 1) / threads;  // 6144

    eme_zero_kernel<<<1, 1>>>();
    eme_main_kernel<<<blocks, threads>>>(y, n_windows);
    eme_finish_kernel<<<1, 1>>>(out);
}

// round 2
// speedup vs baseline: 1.0494x; 1.0494x over previous
#include <cuda_runtime.h>
#include <math_constants.h>

// Statically-initialized accumulators; the last block resets them after use,
// so every graph replay sees zeros. No cudaMalloc, no extra launches.
__device__ double g_eme_sum = 0.0;
__device__ unsigned int g_eme_count = 0u;

// One thread per 8x8 window. Input logical shape (32,3,1024,1024) fp32,
// treated as 96 images of 1024x1024. Windows per image: 128x128.
// Grid: 6144 blocks x 256 threads = 1,572,864 windows exactly.
__global__ __launch_bounds__(256) void eme_fused_kernel(
    const float* __restrict__ y, float* __restrict__ out)
{
    const int w = blockIdx.x * 256 + threadIdx.x;

    const int img = w >> 14;          // 16384 windows per image
    const int rem = w & 16383;
    const int wy  = rem >> 7;         // window row 0..127
    const int wx  = rem & 127;        // window col 0..127

    const float4* __restrict__ p = reinterpret_cast<const float4*>(
        y + (size_t)img * 1048576u + (size_t)wy * 8192u + (size_t)wx * 8u);
    // image row stride = 1024 floats = 256 float4

    float mx = -CUDART_INF_F;
    float mn =  CUDART_INF_F;
    #pragma unroll
    for (int r = 0; r < 8; r++) {
        float4 a = __ldcs(&p[r * 256]);
        float4 b = __ldcs(&p[r * 256 + 1]);
        mx = fmaxf(mx, fmaxf(fmaxf(a.x, a.y), fmaxf(a.z, a.w)));
        mn = fminf(mn, fminf(fminf(a.x, a.y), fminf(a.z, a.w)));
        mx = fmaxf(mx, fmaxf(fmaxf(b.x, b.y), fmaxf(b.z, b.w)));
        mn = fminf(mn, fminf(fminf(b.x, b.y), fminf(b.z, b.w)));
    }

    float val = 0.0f;
    if (mx != mn) {
        val = 20.0f * logf(mx / (mn + 1e-4f));
    }

    // Intra-warp reduction.
    #pragma unroll
    for (int o = 16; o > 0; o >>= 1)
        val += __shfl_xor_sync(0xffffffffu, val, o);

    __shared__ float warp_sums[8];
    const int lane = threadIdx.x & 31;
    const int wid  = threadIdx.x >> 5;
    if (lane == 0) warp_sums[wid] = val;
    __syncthreads();

    if (wid == 0) {
        float v = (lane < 8) ? warp_sums[lane] : 0.0f;
        #pragma unroll
        for (int o = 4; o > 0; o >>= 1)
            v += __shfl_xor_sync(0xffffffffu, v, o);

        if (lane == 0) {
            atomicAdd(&g_eme_sum, (double)v);
            __threadfence();
            unsigned int done = atomicAdd(&g_eme_count, 1u);
            if (done == gridDim.x - 1u) {
                // All partials visible (each block fenced before incrementing).
                double s = g_eme_sum;
                // result = sum / (B * row * col / (w*w)) = sum / 524288
                out[0] = (float)(s * (1.0 / 524288.0));
                // Reset for the next graph replay.
                g_eme_sum = 0.0;
                g_eme_count = 0u;
            }
        }
    }
}

extern "C" void kernel_launch(void* const* d_in, const int* in_sizes, int n_in,
                              void* d_out, int out_size)
{
    const float* y = (const float*)d_in[0];
    float* out = (float*)d_out;

    const int n_windows = 32 * 3 * 128 * 128;  // 1,572,864
    const int threads = 256;
    const int blocks = n_windows / threads;    // 6144, exact

    eme_fused_kernel<<<blocks, threads>>>(y, out);
}